// round 1
// baseline (speedup 1.0000x reference)
#include <cuda_runtime.h>
#include <math.h>

// nGPT block: B=8, T=1024, C=1024, H=16, D=64
#define BT   8192          // B*T tokens
#define CDIM 1024
#define NH   16
#define HD   64

// ---- scratch carve (floats) inside one device global ----
#define OFF_INV 0                          // 4*1024 inverse column norms (q,k,v,o)
#define OFF_Q   4096
#define OFF_K   (OFF_Q  + BT*CDIM)
#define OFF_V   (OFF_K  + BT*CDIM)
#define OFF_Y   (OFF_V  + BT*CDIM)
#define OFF_T1  (OFF_Y  + BT*CDIM)         // h_att / h_mlp
#define OFF_H2  (OFF_T1 + BT*CDIM)         // h after attention residual
#define OFF_UV  (OFF_H2 + BT*CDIM)         // 8192 x 8192
#define OFF_X   (OFF_UV + BT*8*CDIM)       // 8192 x 4096
#define BUF_TOTAL (OFF_X + BT*4*CDIM)      // 150,999,040 floats (~604 MB)

__device__ float g_buf[BUF_TOTAL];

// ---------------------------------------------------------------------------
// inverse column norms of W [C,C] row-major: inv[j] = 1/||W[:,j]||
// grid (C/32, 4 matrices), block 256 (8x32)
// ---------------------------------------------------------------------------
__global__ void colnorm_kernel(const float* __restrict__ Wq, const float* __restrict__ Wk,
                               const float* __restrict__ Wv, const float* __restrict__ Wo,
                               float* __restrict__ inv)
{
    int m = blockIdx.y;
    const float* W = (m == 0) ? Wq : (m == 1) ? Wk : (m == 2) ? Wv : Wo;
    int tx = threadIdx.x & 31;
    int ty = threadIdx.x >> 5;
    int col = blockIdx.x * 32 + tx;
    float s = 0.f;
    for (int i = ty; i < CDIM; i += 8) {
        float w = W[i * CDIM + col];
        s += w * w;
    }
    __shared__ float sm[8][32];
    sm[ty][tx] = s;
    __syncthreads();
    if (ty == 0) {
        float tot = 0.f;
        #pragma unroll
        for (int r = 0; r < 8; r++) tot += sm[r][tx];
        inv[m * CDIM + col] = rsqrtf(tot);
    }
}

// ---------------------------------------------------------------------------
// SGEMM NT: C[m,n] = sum_k A[m,k] * B[n,k] * (SCALE_A ? scl[k] : 1)
// A [M,K], B [N,K], both row-major. BM=BN=128, BK=8, 256 threads, 8x8 microtile.
// Requires M%128==0, N%128==0, K%8==0 (all true here).
// ---------------------------------------------------------------------------
template <bool SCALE_A>
__global__ void __launch_bounds__(256) sgemm_nt_kernel(
    const float* __restrict__ A, const float* __restrict__ Bm,
    const float* __restrict__ scl, float* __restrict__ Cc,
    int M, int N, int K)
{
    const int BK = 8;
    __shared__ float As[BK][128];
    __shared__ float Bs[BK][128];
    int tid  = threadIdx.x;
    int crow = blockIdx.y * 128;
    int ccol = blockIdx.x * 128;
    int tr = tid >> 4;          // 0..15
    int tc = tid & 15;          // 0..15
    int lr = tid >> 1;          // 0..127 tile row for loads
    int lc = (tid & 1) * 4;     // 0 or 4 (float4 within BK)

    const float* Ap = A  + (size_t)(crow + lr) * K + lc;
    const float* Bp = Bm + (size_t)(ccol + lr) * K + lc;

    float acc[8][8];
    #pragma unroll
    for (int i = 0; i < 8; i++)
        #pragma unroll
        for (int j = 0; j < 8; j++) acc[i][j] = 0.f;

    for (int k0 = 0; k0 < K; k0 += BK) {
        float4 a4 = *(const float4*)(Ap + k0);
        float4 b4 = *(const float4*)(Bp + k0);
        if (SCALE_A) {
            float4 s4 = *(const float4*)(scl + k0 + lc);
            a4.x *= s4.x; a4.y *= s4.y; a4.z *= s4.z; a4.w *= s4.w;
        }
        __syncthreads();
        As[lc + 0][lr] = a4.x; As[lc + 1][lr] = a4.y;
        As[lc + 2][lr] = a4.z; As[lc + 3][lr] = a4.w;
        Bs[lc + 0][lr] = b4.x; Bs[lc + 1][lr] = b4.y;
        Bs[lc + 2][lr] = b4.z; Bs[lc + 3][lr] = b4.w;
        __syncthreads();
        #pragma unroll
        for (int kk = 0; kk < BK; kk++) {
            float ra[8], rb[8];
            *(float4*)&ra[0] = *(const float4*)&As[kk][tr * 8];
            *(float4*)&ra[4] = *(const float4*)&As[kk][tr * 8 + 4];
            *(float4*)&rb[0] = *(const float4*)&Bs[kk][tc * 8];
            *(float4*)&rb[4] = *(const float4*)&Bs[kk][tc * 8 + 4];
            #pragma unroll
            for (int i = 0; i < 8; i++)
                #pragma unroll
                for (int j = 0; j < 8; j++)
                    acc[i][j] += ra[i] * rb[j];
        }
    }
    #pragma unroll
    for (int i = 0; i < 8; i++) {
        size_t base = (size_t)(crow + tr * 8 + i) * N + ccol + tc * 8;
        *(float4*)&Cc[base]     = make_float4(acc[i][0], acc[i][1], acc[i][2], acc[i][3]);
        *(float4*)&Cc[base + 4] = make_float4(acc[i][4], acc[i][5], acc[i][6], acc[i][7]);
    }
}

// ---------------------------------------------------------------------------
// Per-(token,head) L2-normalize q and k over head_dim=64, apply sqk*32
// (SQK_INIT/BASE_SCALE) and fold the softmax scale sqrt(D)=8 into q.
// grid BT, block 256 (thread t owns 4 contiguous cols; 16 threads per head).
// ---------------------------------------------------------------------------
__global__ void qknorm_kernel(float* __restrict__ q, float* __restrict__ k,
                              const float* __restrict__ sqk)
{
    int t = blockIdx.x, tid = threadIdx.x;
    float4* q4 = (float4*)q + (size_t)t * 256;
    float4* k4 = (float4*)k + (size_t)t * 256;
    float4 sc = ((const float4*)sqk)[tid];

    float4 v = q4[tid];
    float ss = v.x * v.x + v.y * v.y + v.z * v.z + v.w * v.w;
    #pragma unroll
    for (int off = 8; off >= 1; off >>= 1) ss += __shfl_xor_sync(0xffffffffu, ss, off);
    float r = rsqrtf(ss) * 32.f * 8.f;                 // sqk scale * softmax scale
    v.x *= r * sc.x; v.y *= r * sc.y; v.z *= r * sc.z; v.w *= r * sc.w;
    q4[tid] = v;

    v = k4[tid];
    ss = v.x * v.x + v.y * v.y + v.z * v.z + v.w * v.w;
    #pragma unroll
    for (int off = 8; off >= 1; off >>= 1) ss += __shfl_xor_sync(0xffffffffu, ss, off);
    r = rsqrtf(ss) * 32.f;
    v.x *= r * sc.x; v.y *= r * sc.y; v.z *= r * sc.z; v.w *= r * sc.w;
    k4[tid] = v;
}

// ---------------------------------------------------------------------------
// Flash attention (non-causal), D=64, 64 q-rows per block, 64-key tiles,
// online softmax. grid (T/64=16, B*H=128), 256 threads, dynamic smem 49408B.
// y written as [token, h*64+d] (matches transpose+reshape in reference).
// ---------------------------------------------------------------------------
__global__ void __launch_bounds__(256) attn_kernel(
    const float* __restrict__ q, const float* __restrict__ k,
    const float* __restrict__ v, float* __restrict__ y)
{
    extern __shared__ float smd[];
    float* Qs = smd;             // [64][64]
    float* KP = smd + 4096;      // Kt[d*65+j], reused as P[i*65+j]
    float* Vs = smd + 8256;      // [64][64]

    int tid = threadIdx.x;
    int tx = tid & 15, ty = tid >> 4;
    int bh    = blockIdx.y;
    int tbase = (bh >> 4) * 1024;          // batch offset in tokens
    int cb    = (bh & 15) * 64;            // head column base
    int tq0   = tbase + blockIdx.x * 64;

    #pragma unroll
    for (int r = 0; r < 4; r++) {
        int idx = tid + r * 256;
        int i = idx >> 4, d4 = idx & 15;
        *(float4*)&Qs[i * 64 + d4 * 4] =
            *(const float4*)&q[(size_t)(tq0 + i) * CDIM + cb + d4 * 4];
    }

    float acc[4][4], mrow[4], lrow[4];
    #pragma unroll
    for (int r = 0; r < 4; r++) {
        mrow[r] = -1e30f; lrow[r] = 0.f;
        #pragma unroll
        for (int c = 0; c < 4; c++) acc[r][c] = 0.f;
    }

    for (int kt = 0; kt < 16; kt++) {
        int tk0 = tbase + kt * 64;
        __syncthreads();   // previous tile's P/V fully consumed
        #pragma unroll
        for (int r = 0; r < 4; r++) {
            int idx = tid + r * 256;
            int j = idx >> 4, d4 = idx & 15;
            float4 kv = *(const float4*)&k[(size_t)(tk0 + j) * CDIM + cb + d4 * 4];
            KP[(d4 * 4 + 0) * 65 + j] = kv.x;
            KP[(d4 * 4 + 1) * 65 + j] = kv.y;
            KP[(d4 * 4 + 2) * 65 + j] = kv.z;
            KP[(d4 * 4 + 3) * 65 + j] = kv.w;
            *(float4*)&Vs[j * 64 + d4 * 4] =
                *(const float4*)&v[(size_t)(tk0 + j) * CDIM + cb + d4 * 4];
        }
        __syncthreads();

        float s[4][4];
        #pragma unroll
        for (int r = 0; r < 4; r++)
            #pragma unroll
            for (int c = 0; c < 4; c++) s[r][c] = 0.f;
        #pragma unroll 8
        for (int d = 0; d < 64; d++) {
            float qr[4], kc[4];
            #pragma unroll
            for (int r = 0; r < 4; r++) qr[r] = Qs[(4 * ty + r) * 64 + d];
            #pragma unroll
            for (int c = 0; c < 4; c++) kc[c] = KP[d * 65 + 4 * tx + c];
            #pragma unroll
            for (int r = 0; r < 4; r++)
                #pragma unroll
                for (int c = 0; c < 4; c++) s[r][c] += qr[r] * kc[c];
        }

        // online softmax (row groups = 16 lanes sharing ty; xor<=8 stays in group)
        float co[4];
        #pragma unroll
        for (int r = 0; r < 4; r++) {
            float rm = fmaxf(fmaxf(s[r][0], s[r][1]), fmaxf(s[r][2], s[r][3]));
            #pragma unroll
            for (int off = 8; off >= 1; off >>= 1)
                rm = fmaxf(rm, __shfl_xor_sync(0xffffffffu, rm, off));
            float mn = fmaxf(mrow[r], rm);
            co[r] = __expf(mrow[r] - mn);
            float ls = 0.f;
            #pragma unroll
            for (int c = 0; c < 4; c++) {
                float e = __expf(s[r][c] - mn);
                s[r][c] = e; ls += e;
            }
            #pragma unroll
            for (int off = 8; off >= 1; off >>= 1)
                ls += __shfl_xor_sync(0xffffffffu, ls, off);
            lrow[r] = lrow[r] * co[r] + ls;
            mrow[r] = mn;
        }

        __syncthreads();   // all threads done reading KP as Kt
        #pragma unroll
        for (int r = 0; r < 4; r++)
            #pragma unroll
            for (int c = 0; c < 4; c++)
                KP[(4 * ty + r) * 65 + 4 * tx + c] = s[r][c];
        __syncthreads();

        #pragma unroll
        for (int r = 0; r < 4; r++)
            #pragma unroll
            for (int c = 0; c < 4; c++) acc[r][c] *= co[r];

        #pragma unroll 8
        for (int j = 0; j < 64; j++) {
            float pr[4], vc[4];
            #pragma unroll
            for (int r = 0; r < 4; r++) pr[r] = KP[(4 * ty + r) * 65 + j];
            #pragma unroll
            for (int c = 0; c < 4; c++) vc[c] = Vs[j * 64 + 4 * tx + c];
            #pragma unroll
            for (int r = 0; r < 4; r++)
                #pragma unroll
                for (int c = 0; c < 4; c++) acc[r][c] += pr[r] * vc[c];
        }
    }

    #pragma unroll
    for (int r = 0; r < 4; r++) {
        float li = 1.f / lrow[r];
        *(float4*)&y[(size_t)(tq0 + 4 * ty + r) * CDIM + cb + 4 * tx] =
            make_float4(acc[r][0] * li, acc[r][1] * li, acc[r][2] * li, acc[r][3] * li);
    }
}

// ---------------------------------------------------------------------------
// x[t,m] = (suv[m]*32*uv[t,m]) * silu(suv[m+4096]*32*uv[t,m+4096]),  m<4096
// ---------------------------------------------------------------------------
__global__ void silu_kernel(const float* __restrict__ uv, const float* __restrict__ suv,
                            float* __restrict__ x)
{
    int idx = blockIdx.x * 256 + threadIdx.x;      // float4 index, total 8192*1024
    int t = idx >> 10, m4 = idx & 1023;
    const float4* uv4 = (const float4*)uv;
    const float4* s4  = (const float4*)suv;
    float4 u  = uv4[(size_t)t * 2048 + m4];
    float4 g  = uv4[(size_t)t * 2048 + 1024 + m4];
    float4 su = s4[m4];
    float4 sg = s4[1024 + m4];
    float4 o;
    float gx;
    gx = g.x * sg.x * 32.f; o.x = (u.x * su.x * 32.f) * gx / (1.f + __expf(-gx));
    gx = g.y * sg.y * 32.f; o.y = (u.y * su.y * 32.f) * gx / (1.f + __expf(-gx));
    gx = g.z * sg.z * 32.f; o.z = (u.z * su.z * 32.f) * gx / (1.f + __expf(-gx));
    gx = g.w * sg.w * 32.f; o.w = (u.w * su.w * 32.f) * gx / (1.f + __expf(-gx));
    ((float4*)x)[(size_t)t * 1024 + m4] = o;
}

// ---------------------------------------------------------------------------
// out = justnorm( justnorm(h) + |alpha*1.6| * (justnorm(hb) - justnorm(h)) )
// grid BT, block 256 (one float4 per thread).
// ---------------------------------------------------------------------------
__global__ void residual_kernel(const float* __restrict__ hin, const float* __restrict__ hb,
                                const float* __restrict__ alpha, float* __restrict__ out)
{
    int t = blockIdx.x, tid = threadIdx.x;
    float4 a = ((const float4*)hin)[(size_t)t * 256 + tid];
    float4 b = ((const float4*)hb)[(size_t)t * 256 + tid];
    float s1 = a.x * a.x + a.y * a.y + a.z * a.z + a.w * a.w;
    float s2 = b.x * b.x + b.y * b.y + b.z * b.z + b.w * b.w;
    #pragma unroll
    for (int off = 16; off >= 1; off >>= 1) {
        s1 += __shfl_xor_sync(0xffffffffu, s1, off);
        s2 += __shfl_xor_sync(0xffffffffu, s2, off);
    }
    __shared__ float red1[8], red2[8];
    int w = tid >> 5, lane = tid & 31;
    if (lane == 0) { red1[w] = s1; red2[w] = s2; }
    __syncthreads();
    float t1 = 0.f, t2 = 0.f;
    #pragma unroll
    for (int i = 0; i < 8; i++) { t1 += red1[i]; t2 += red2[i]; }
    float r1 = rsqrtf(t1), r2 = rsqrtf(t2);

    float4 al = ((const float4*)alpha)[tid];
    float4 u;
    u.x = a.x * r1 + fabsf(al.x * 1.6f) * (b.x * r2 - a.x * r1);
    u.y = a.y * r1 + fabsf(al.y * 1.6f) * (b.y * r2 - a.y * r1);
    u.z = a.z * r1 + fabsf(al.z * 1.6f) * (b.z * r2 - a.z * r1);
    u.w = a.w * r1 + fabsf(al.w * 1.6f) * (b.w * r2 - a.w * r1);

    float s3 = u.x * u.x + u.y * u.y + u.z * u.z + u.w * u.w;
    #pragma unroll
    for (int off = 16; off >= 1; off >>= 1) s3 += __shfl_xor_sync(0xffffffffu, s3, off);
    __syncthreads();
    if (lane == 0) red1[w] = s3;
    __syncthreads();
    float t3 = 0.f;
    #pragma unroll
    for (int i = 0; i < 8; i++) t3 += red1[i];
    float r3 = rsqrtf(t3);
    ((float4*)out)[(size_t)t * 256 + tid] =
        make_float4(u.x * r3, u.y * r3, u.z * r3, u.w * r3);
}

// ---------------------------------------------------------------------------
extern "C" void kernel_launch(void* const* d_in, const int* in_sizes, int n_in,
                              void* d_out, int out_size)
{
    (void)in_sizes; (void)n_in; (void)out_size;
    const float* h     = (const float*)d_in[0];
    const float* Wq    = (const float*)d_in[1];
    const float* Wk    = (const float*)d_in[2];
    const float* Wv    = (const float*)d_in[3];
    const float* Wo    = (const float*)d_in[4];
    const float* Wfc   = (const float*)d_in[5];
    const float* Wproj = (const float*)d_in[6];
    const float* sqk   = (const float*)d_in[7];
    const float* suv   = (const float*)d_in[8];
    const float* a_att = (const float*)d_in[9];
    const float* a_mlp = (const float*)d_in[10];
    float* out = (float*)d_out;

    float* buf = nullptr;
    cudaGetSymbolAddress((void**)&buf, g_buf);
    float* inv = buf + OFF_INV;
    float* qb  = buf + OFF_Q;
    float* kb  = buf + OFF_K;
    float* vb  = buf + OFF_V;
    float* yb  = buf + OFF_Y;
    float* t1  = buf + OFF_T1;
    float* h2  = buf + OFF_H2;
    float* uvb = buf + OFF_UV;
    float* xb  = buf + OFF_X;

    cudaFuncSetAttribute(attn_kernel, cudaFuncAttributeMaxDynamicSharedMemorySize, 49408);

    // weight column norms
    colnorm_kernel<<<dim3(32, 4), 256>>>(Wq, Wk, Wv, Wo, inv);

    // q,k,v projections (norm folded via inv[k] on A)
    dim3 gqkv(CDIM / 128, BT / 128);
    sgemm_nt_kernel<true><<<gqkv, 256>>>(h, Wq, inv,            qb, BT, CDIM, CDIM);
    sgemm_nt_kernel<true><<<gqkv, 256>>>(h, Wk, inv + CDIM,     kb, BT, CDIM, CDIM);
    sgemm_nt_kernel<true><<<gqkv, 256>>>(h, Wv, inv + 2 * CDIM, vb, BT, CDIM, CDIM);

    // per-head normalize q,k (+sqk*32, softmax*8 folded into q)
    qknorm_kernel<<<BT, 256>>>(qb, kb, sqk);

    // attention
    attn_kernel<<<dim3(16, 128), 256, 49408>>>(qb, kb, vb, yb);

    // o projection
    sgemm_nt_kernel<true><<<gqkv, 256>>>(yb, Wo, inv + 3 * CDIM, t1, BT, CDIM, CDIM);

    // attention residual lerp-norm
    residual_kernel<<<BT, 256>>>(h, t1, a_att, h2);

    // MLP
    sgemm_nt_kernel<false><<<dim3(8 * CDIM / 128, BT / 128), 256>>>(h2, Wfc, nullptr, uvb, BT, 8 * CDIM, CDIM);
    silu_kernel<<<(BT * 1024) / 256, 256>>>(uvb, suv, xb);
    sgemm_nt_kernel<false><<<dim3(CDIM / 128, BT / 128), 256>>>(xb, Wproj, nullptr, t1, BT, CDIM, 4 * CDIM);

    // MLP residual lerp-norm -> output
    residual_kernel<<<BT, 256>>>(h2, t1, a_mlp, out);
}

// round 2
// speedup vs baseline: 1.9238x; 1.9238x over previous
#include <cuda_runtime.h>
#include <math.h>
#include <stdint.h>

// nGPT block: B=8, T=1024, C=1024, H=16, D=64
#define BT   8192          // B*T tokens
#define CDIM 1024
#define NH   16
#define HD   64

// ---- scratch carve (floats) inside one device global ----
#define OFF_INV 0                          // 4*1024 inverse column norms (q,k,v,o)
#define OFF_Q   4096
#define OFF_K   (OFF_Q  + BT*CDIM)
#define OFF_V   (OFF_K  + BT*CDIM)
#define OFF_Y   (OFF_V  + BT*CDIM)
#define OFF_T1  (OFF_Y  + BT*CDIM)         // h_att / h_mlp
#define OFF_H2  (OFF_T1 + BT*CDIM)         // h after attention residual
#define OFF_UV  (OFF_H2 + BT*CDIM)         // 8192 x 8192
#define OFF_X   (OFF_UV + BT*8*CDIM)       // 8192 x 4096
#define BUF_TOTAL (OFF_X + BT*4*CDIM)

__device__ float g_buf[BUF_TOTAL];

__device__ __forceinline__ uint32_t f2tf32(float f) {
    uint32_t r;
    asm("cvt.rna.tf32.f32 %0, %1;" : "=r"(r) : "f"(f));
    return r;
}

// ---------------------------------------------------------------------------
// inverse column norms of W [C,C] row-major: inv[j] = 1/||W[:,j]||
// ---------------------------------------------------------------------------
__global__ void colnorm_kernel(const float* __restrict__ Wq, const float* __restrict__ Wk,
                               const float* __restrict__ Wv, const float* __restrict__ Wo,
                               float* __restrict__ inv)
{
    int m = blockIdx.y;
    const float* W = (m == 0) ? Wq : (m == 1) ? Wk : (m == 2) ? Wv : Wo;
    int tx = threadIdx.x & 31;
    int ty = threadIdx.x >> 5;
    int col = blockIdx.x * 32 + tx;
    float s = 0.f;
    for (int i = ty; i < CDIM; i += 8) {
        float w = W[i * CDIM + col];
        s += w * w;
    }
    __shared__ float sm[8][32];
    sm[ty][tx] = s;
    __syncthreads();
    if (ty == 0) {
        float tot = 0.f;
        #pragma unroll
        for (int r = 0; r < 8; r++) tot += sm[r][tx];
        inv[m * CDIM + col] = rsqrtf(tot);
    }
}

// ---------------------------------------------------------------------------
// TF32 tensor-core GEMM NT: C[m,n] = sum_k A[m,k]*(SCALE_A?scl[k]:1) * B[n,k]
// A [M,K], B [N,K] row-major. Tile 128x128x32, double-buffered k-major smem,
// 8 warps in 2x4 layout, each warp 64x32 via 4x4 grid of m16n8k8 tf32 mma.
// Requires M%128==0, N%128==0, K%32==0.
// ---------------------------------------------------------------------------
#define RS 132   // padded row stride (floats) for k-major smem [32][RS]

template <bool SCALE_A>
__global__ void __launch_bounds__(256) mma_nt_kernel(
    const float* __restrict__ A, const float* __restrict__ Bm,
    const float* __restrict__ scl, float* __restrict__ Cc,
    int M, int N, int K)
{
    extern __shared__ uint32_t smu[];
    uint32_t* As = smu;               // [2][32][RS]
    uint32_t* Bs = smu + 2 * 32 * RS; // [2][32][RS]

    const int tid  = threadIdx.x;
    const int lane = tid & 31;
    const int warp = tid >> 5;
    const int wm = warp & 1;          // 2 warps along M
    const int wn = warp >> 1;         // 4 warps along N
    const int crow = blockIdx.y * 128;
    const int ccol = blockIdx.x * 128;

    const int grow = tid >> 3;        // 0..31 (base tile row for ldg)
    const int kc   = tid & 7;         // float4 index within BK=32

    const float* Aptr = A  + (size_t)(crow + grow) * K + kc * 4;
    const float* Bptr = Bm + (size_t)(ccol + grow) * K + kc * 4;

    float4 ar[4], br[4], s4;

    float c[4][4][4];
    #pragma unroll
    for (int i = 0; i < 4; i++)
        #pragma unroll
        for (int j = 0; j < 4; j++)
            #pragma unroll
            for (int e = 0; e < 4; e++) c[i][j][e] = 0.f;

    const int nt = K / 32;

    // ---- prologue: load tile 0 ----
    {
        const int k0 = 0;
        #pragma unroll
        for (int r = 0; r < 4; r++) {
            ar[r] = *(const float4*)(Aptr + (size_t)(32 * r) * K + k0);
            br[r] = *(const float4*)(Bptr + (size_t)(32 * r) * K + k0);
        }
        if (SCALE_A) s4 = *(const float4*)(scl + k0 + kc * 4);
        uint32_t* a0 = As;
        uint32_t* b0 = Bs;
        #pragma unroll
        for (int r = 0; r < 4; r++) {
            float av[4] = {ar[r].x, ar[r].y, ar[r].z, ar[r].w};
            float bv[4] = {br[r].x, br[r].y, br[r].z, br[r].w};
            float sv[4];
            if (SCALE_A) { sv[0]=s4.x; sv[1]=s4.y; sv[2]=s4.z; sv[3]=s4.w; }
            #pragma unroll
            for (int j = 0; j < 4; j++) {
                float a = SCALE_A ? av[j] * sv[j] : av[j];
                a0[(kc * 4 + j) * RS + grow + 32 * r] = f2tf32(a);
                b0[(kc * 4 + j) * RS + grow + 32 * r] = f2tf32(bv[j]);
            }
        }
    }
    __syncthreads();

    for (int t = 0; t < nt; t++) {
        const int cur = t & 1;
        // prefetch next tile (global -> regs)
        if (t + 1 < nt) {
            const int k0 = (t + 1) * 32;
            #pragma unroll
            for (int r = 0; r < 4; r++) {
                ar[r] = *(const float4*)(Aptr + (size_t)(32 * r) * K + k0);
                br[r] = *(const float4*)(Bptr + (size_t)(32 * r) * K + k0);
            }
            if (SCALE_A) s4 = *(const float4*)(scl + k0 + kc * 4);
        }

        // compute on current buffer
        const uint32_t* ab = As + cur * 32 * RS;
        const uint32_t* bb = Bs + cur * 32 * RS;
        #pragma unroll
        for (int ks = 0; ks < 4; ks++) {
            const int kb = ks * 8;
            uint32_t afr[4][4];
            uint32_t bfr[4][2];
            const int arow = wm * 64 + (lane >> 2);
            const int akc  = kb + (lane & 3);
            #pragma unroll
            for (int mi = 0; mi < 4; mi++) {
                afr[mi][0] = ab[(akc    ) * RS + arow + mi * 16    ];
                afr[mi][1] = ab[(akc    ) * RS + arow + mi * 16 + 8];
                afr[mi][2] = ab[(akc + 4) * RS + arow + mi * 16    ];
                afr[mi][3] = ab[(akc + 4) * RS + arow + mi * 16 + 8];
            }
            const int bnn = wn * 32 + (lane >> 2);
            #pragma unroll
            for (int nj = 0; nj < 4; nj++) {
                bfr[nj][0] = bb[(akc    ) * RS + bnn + nj * 8];
                bfr[nj][1] = bb[(akc + 4) * RS + bnn + nj * 8];
            }
            #pragma unroll
            for (int mi = 0; mi < 4; mi++)
                #pragma unroll
                for (int nj = 0; nj < 4; nj++) {
                    asm volatile(
                        "mma.sync.aligned.m16n8k8.row.col.f32.tf32.tf32.f32 "
                        "{%0,%1,%2,%3}, {%4,%5,%6,%7}, {%8,%9}, {%0,%1,%2,%3};"
                        : "+f"(c[mi][nj][0]), "+f"(c[mi][nj][1]),
                          "+f"(c[mi][nj][2]), "+f"(c[mi][nj][3])
                        : "r"(afr[mi][0]), "r"(afr[mi][1]),
                          "r"(afr[mi][2]), "r"(afr[mi][3]),
                          "r"(bfr[nj][0]), "r"(bfr[nj][1]));
                }
        }

        // store prefetched tile into the other buffer
        if (t + 1 < nt) {
            uint32_t* a1 = As + (1 - cur) * 32 * RS;
            uint32_t* b1 = Bs + (1 - cur) * 32 * RS;
            #pragma unroll
            for (int r = 0; r < 4; r++) {
                float av[4] = {ar[r].x, ar[r].y, ar[r].z, ar[r].w};
                float bv[4] = {br[r].x, br[r].y, br[r].z, br[r].w};
                float sv[4];
                if (SCALE_A) { sv[0]=s4.x; sv[1]=s4.y; sv[2]=s4.z; sv[3]=s4.w; }
                #pragma unroll
                for (int j = 0; j < 4; j++) {
                    float a = SCALE_A ? av[j] * sv[j] : av[j];
                    a1[(kc * 4 + j) * RS + grow + 32 * r] = f2tf32(a);
                    b1[(kc * 4 + j) * RS + grow + 32 * r] = f2tf32(bv[j]);
                }
            }
            __syncthreads();
        }
    }

    // ---- epilogue ----
    #pragma unroll
    for (int mi = 0; mi < 4; mi++) {
        const int r0 = crow + wm * 64 + mi * 16 + (lane >> 2);
        #pragma unroll
        for (int nj = 0; nj < 4; nj++) {
            const int c0 = ccol + wn * 32 + nj * 8 + 2 * (lane & 3);
            *(float2*)&Cc[(size_t)r0 * N + c0] =
                make_float2(c[mi][nj][0], c[mi][nj][1]);
            *(float2*)&Cc[(size_t)(r0 + 8) * N + c0] =
                make_float2(c[mi][nj][2], c[mi][nj][3]);
        }
    }
}

#define MMA_SMEM (2 * 2 * 32 * RS * 4)

// ---------------------------------------------------------------------------
// Per-(token,head) L2-normalize q and k over head_dim=64, apply sqk*32,
// fold softmax scale sqrt(D)=8 into q.
// ---------------------------------------------------------------------------
__global__ void qknorm_kernel(float* __restrict__ q, float* __restrict__ k,
                              const float* __restrict__ sqk)
{
    int t = blockIdx.x, tid = threadIdx.x;
    float4* q4 = (float4*)q + (size_t)t * 256;
    float4* k4 = (float4*)k + (size_t)t * 256;
    float4 sc = ((const float4*)sqk)[tid];

    float4 v = q4[tid];
    float ss = v.x * v.x + v.y * v.y + v.z * v.z + v.w * v.w;
    #pragma unroll
    for (int off = 8; off >= 1; off >>= 1) ss += __shfl_xor_sync(0xffffffffu, ss, off);
    float r = rsqrtf(ss) * 32.f * 8.f;
    v.x *= r * sc.x; v.y *= r * sc.y; v.z *= r * sc.z; v.w *= r * sc.w;
    q4[tid] = v;

    v = k4[tid];
    ss = v.x * v.x + v.y * v.y + v.z * v.z + v.w * v.w;
    #pragma unroll
    for (int off = 8; off >= 1; off >>= 1) ss += __shfl_xor_sync(0xffffffffu, ss, off);
    r = rsqrtf(ss) * 32.f;
    v.x *= r * sc.x; v.y *= r * sc.y; v.z *= r * sc.z; v.w *= r * sc.w;
    k4[tid] = v;
}

// ---------------------------------------------------------------------------
// Flash attention (non-causal), D=64, 64 q-rows/block, 64-key tiles, online
// softmax. grid (16, B*H=128), 256 threads, dyn smem 49408B.
// ---------------------------------------------------------------------------
__global__ void __launch_bounds__(256) attn_kernel(
    const float* __restrict__ q, const float* __restrict__ k,
    const float* __restrict__ v, float* __restrict__ y)
{
    extern __shared__ float smd[];
    float* Qs = smd;             // [64][64]
    float* KP = smd + 4096;      // Kt[d*65+j], reused as P[i*65+j]
    float* Vs = smd + 8256;      // [64][64]

    int tid = threadIdx.x;
    int tx = tid & 15, ty = tid >> 4;
    int bh    = blockIdx.y;
    int tbase = (bh >> 4) * 1024;
    int cb    = (bh & 15) * 64;
    int tq0   = tbase + blockIdx.x * 64;

    #pragma unroll
    for (int r = 0; r < 4; r++) {
        int idx = tid + r * 256;
        int i = idx >> 4, d4 = idx & 15;
        *(float4*)&Qs[i * 64 + d4 * 4] =
            *(const float4*)&q[(size_t)(tq0 + i) * CDIM + cb + d4 * 4];
    }

    float acc[4][4], mrow[4], lrow[4];
    #pragma unroll
    for (int r = 0; r < 4; r++) {
        mrow[r] = -1e30f; lrow[r] = 0.f;
        #pragma unroll
        for (int c = 0; c < 4; c++) acc[r][c] = 0.f;
    }

    for (int kt = 0; kt < 16; kt++) {
        int tk0 = tbase + kt * 64;
        __syncthreads();
        #pragma unroll
        for (int r = 0; r < 4; r++) {
            int idx = tid + r * 256;
            int j = idx >> 4, d4 = idx & 15;
            float4 kv = *(const float4*)&k[(size_t)(tk0 + j) * CDIM + cb + d4 * 4];
            KP[(d4 * 4 + 0) * 65 + j] = kv.x;
            KP[(d4 * 4 + 1) * 65 + j] = kv.y;
            KP[(d4 * 4 + 2) * 65 + j] = kv.z;
            KP[(d4 * 4 + 3) * 65 + j] = kv.w;
            *(float4*)&Vs[j * 64 + d4 * 4] =
                *(const float4*)&v[(size_t)(tk0 + j) * CDIM + cb + d4 * 4];
        }
        __syncthreads();

        float s[4][4];
        #pragma unroll
        for (int r = 0; r < 4; r++)
            #pragma unroll
            for (int c = 0; c < 4; c++) s[r][c] = 0.f;
        #pragma unroll 8
        for (int d = 0; d < 64; d++) {
            float qr[4], kcv[4];
            #pragma unroll
            for (int r = 0; r < 4; r++) qr[r] = Qs[(4 * ty + r) * 64 + d];
            #pragma unroll
            for (int c = 0; c < 4; c++) kcv[c] = KP[d * 65 + 4 * tx + c];
            #pragma unroll
            for (int r = 0; r < 4; r++)
                #pragma unroll
                for (int c = 0; c < 4; c++) s[r][c] += qr[r] * kcv[c];
        }

        float co[4];
        #pragma unroll
        for (int r = 0; r < 4; r++) {
            float rm = fmaxf(fmaxf(s[r][0], s[r][1]), fmaxf(s[r][2], s[r][3]));
            #pragma unroll
            for (int off = 8; off >= 1; off >>= 1)
                rm = fmaxf(rm, __shfl_xor_sync(0xffffffffu, rm, off));
            float mn = fmaxf(mrow[r], rm);
            co[r] = __expf(mrow[r] - mn);
            float ls = 0.f;
            #pragma unroll
            for (int c = 0; c < 4; c++) {
                float e = __expf(s[r][c] - mn);
                s[r][c] = e; ls += e;
            }
            #pragma unroll
            for (int off = 8; off >= 1; off >>= 1)
                ls += __shfl_xor_sync(0xffffffffu, ls, off);
            lrow[r] = lrow[r] * co[r] + ls;
            mrow[r] = mn;
        }

        __syncthreads();
        #pragma unroll
        for (int r = 0; r < 4; r++)
            #pragma unroll
            for (int c = 0; c < 4; c++)
                KP[(4 * ty + r) * 65 + 4 * tx + c] = s[r][c];
        __syncthreads();

        #pragma unroll
        for (int r = 0; r < 4; r++)
            #pragma unroll
            for (int c = 0; c < 4; c++) acc[r][c] *= co[r];

        #pragma unroll 8
        for (int j = 0; j < 64; j++) {
            float pr[4], vc[4];
            #pragma unroll
            for (int r = 0; r < 4; r++) pr[r] = KP[(4 * ty + r) * 65 + j];
            #pragma unroll
            for (int c = 0; c < 4; c++) vc[c] = Vs[j * 64 + 4 * tx + c];
            #pragma unroll
            for (int r = 0; r < 4; r++)
                #pragma unroll
                for (int c = 0; c < 4; c++) acc[r][c] += pr[r] * vc[c];
        }
    }

    #pragma unroll
    for (int r = 0; r < 4; r++) {
        float li = 1.f / lrow[r];
        *(float4*)&y[(size_t)(tq0 + 4 * ty + r) * CDIM + cb + 4 * tx] =
            make_float4(acc[r][0] * li, acc[r][1] * li, acc[r][2] * li, acc[r][3] * li);
    }
}

// ---------------------------------------------------------------------------
// x[t,m] = (suv[m]*32*uv[t,m]) * silu(suv[m+4096]*32*uv[t,m+4096])
// ---------------------------------------------------------------------------
__global__ void silu_kernel(const float* __restrict__ uv, const float* __restrict__ suv,
                            float* __restrict__ x)
{
    int idx = blockIdx.x * 256 + threadIdx.x;
    int t = idx >> 10, m4 = idx & 1023;
    const float4* uv4 = (const float4*)uv;
    const float4* s4  = (const float4*)suv;
    float4 u  = uv4[(size_t)t * 2048 + m4];
    float4 g  = uv4[(size_t)t * 2048 + 1024 + m4];
    float4 su = s4[m4];
    float4 sg = s4[1024 + m4];
    float4 o;
    float gx;
    gx = g.x * sg.x * 32.f; o.x = (u.x * su.x * 32.f) * gx / (1.f + __expf(-gx));
    gx = g.y * sg.y * 32.f; o.y = (u.y * su.y * 32.f) * gx / (1.f + __expf(-gx));
    gx = g.z * sg.z * 32.f; o.z = (u.z * su.z * 32.f) * gx / (1.f + __expf(-gx));
    gx = g.w * sg.w * 32.f; o.w = (u.w * su.w * 32.f) * gx / (1.f + __expf(-gx));
    ((float4*)x)[(size_t)t * 1024 + m4] = o;
}

// ---------------------------------------------------------------------------
// out = justnorm( justnorm(h) + |alpha*1.6| * (justnorm(hb) - justnorm(h)) )
// ---------------------------------------------------------------------------
__global__ void residual_kernel(const float* __restrict__ hin, const float* __restrict__ hb,
                                const float* __restrict__ alpha, float* __restrict__ out)
{
    int t = blockIdx.x, tid = threadIdx.x;
    float4 a = ((const float4*)hin)[(size_t)t * 256 + tid];
    float4 b = ((const float4*)hb)[(size_t)t * 256 + tid];
    float s1 = a.x * a.x + a.y * a.y + a.z * a.z + a.w * a.w;
    float s2 = b.x * b.x + b.y * b.y + b.z * b.z + b.w * b.w;
    #pragma unroll
    for (int off = 16; off >= 1; off >>= 1) {
        s1 += __shfl_xor_sync(0xffffffffu, s1, off);
        s2 += __shfl_xor_sync(0xffffffffu, s2, off);
    }
    __shared__ float red1[8], red2[8];
    int w = tid >> 5, lane = tid & 31;
    if (lane == 0) { red1[w] = s1; red2[w] = s2; }
    __syncthreads();
    float t1 = 0.f, t2 = 0.f;
    #pragma unroll
    for (int i = 0; i < 8; i++) { t1 += red1[i]; t2 += red2[i]; }
    float r1 = rsqrtf(t1), r2 = rsqrtf(t2);

    float4 al = ((const float4*)alpha)[tid];
    float4 u;
    u.x = a.x * r1 + fabsf(al.x * 1.6f) * (b.x * r2 - a.x * r1);
    u.y = a.y * r1 + fabsf(al.y * 1.6f) * (b.y * r2 - a.y * r1);
    u.z = a.z * r1 + fabsf(al.z * 1.6f) * (b.z * r2 - a.z * r1);
    u.w = a.w * r1 + fabsf(al.w * 1.6f) * (b.w * r2 - a.w * r1);

    float s3 = u.x * u.x + u.y * u.y + u.z * u.z + u.w * u.w;
    #pragma unroll
    for (int off = 16; off >= 1; off >>= 1) s3 += __shfl_xor_sync(0xffffffffu, s3, off);
    __syncthreads();
    if (lane == 0) red1[w] = s3;
    __syncthreads();
    float t3 = 0.f;
    #pragma unroll
    for (int i = 0; i < 8; i++) t3 += red1[i];
    float r3 = rsqrtf(t3);
    ((float4*)out)[(size_t)t * 256 + tid] =
        make_float4(u.x * r3, u.y * r3, u.z * r3, u.w * r3);
}

// ---------------------------------------------------------------------------
extern "C" void kernel_launch(void* const* d_in, const int* in_sizes, int n_in,
                              void* d_out, int out_size)
{
    (void)in_sizes; (void)n_in; (void)out_size;
    const float* h     = (const float*)d_in[0];
    const float* Wq    = (const float*)d_in[1];
    const float* Wk    = (const float*)d_in[2];
    const float* Wv    = (const float*)d_in[3];
    const float* Wo    = (const float*)d_in[4];
    const float* Wfc   = (const float*)d_in[5];
    const float* Wproj = (const float*)d_in[6];
    const float* sqk   = (const float*)d_in[7];
    const float* suv   = (const float*)d_in[8];
    const float* a_att = (const float*)d_in[9];
    const float* a_mlp = (const float*)d_in[10];
    float* out = (float*)d_out;

    float* buf = nullptr;
    cudaGetSymbolAddress((void**)&buf, g_buf);
    float* inv = buf + OFF_INV;
    float* qb  = buf + OFF_Q;
    float* kb  = buf + OFF_K;
    float* vb  = buf + OFF_V;
    float* yb  = buf + OFF_Y;
    float* t1  = buf + OFF_T1;
    float* h2  = buf + OFF_H2;
    float* uvb = buf + OFF_UV;
    float* xb  = buf + OFF_X;

    cudaFuncSetAttribute(attn_kernel, cudaFuncAttributeMaxDynamicSharedMemorySize, 49408);
    cudaFuncSetAttribute(mma_nt_kernel<true>,  cudaFuncAttributeMaxDynamicSharedMemorySize, MMA_SMEM);
    cudaFuncSetAttribute(mma_nt_kernel<false>, cudaFuncAttributeMaxDynamicSharedMemorySize, MMA_SMEM);

    colnorm_kernel<<<dim3(32, 4), 256>>>(Wq, Wk, Wv, Wo, inv);

    dim3 gqkv(CDIM / 128, BT / 128);
    mma_nt_kernel<true><<<gqkv, 256, MMA_SMEM>>>(h, Wq, inv,            qb, BT, CDIM, CDIM);
    mma_nt_kernel<true><<<gqkv, 256, MMA_SMEM>>>(h, Wk, inv + CDIM,     kb, BT, CDIM, CDIM);
    mma_nt_kernel<true><<<gqkv, 256, MMA_SMEM>>>(h, Wv, inv + 2 * CDIM, vb, BT, CDIM, CDIM);

    qknorm_kernel<<<BT, 256>>>(qb, kb, sqk);

    attn_kernel<<<dim3(16, 128), 256, 49408>>>(qb, kb, vb, yb);

    mma_nt_kernel<true><<<gqkv, 256, MMA_SMEM>>>(yb, Wo, inv + 3 * CDIM, t1, BT, CDIM, CDIM);

    residual_kernel<<<BT, 256>>>(h, t1, a_att, h2);

    mma_nt_kernel<false><<<dim3(8 * CDIM / 128, BT / 128), 256, MMA_SMEM>>>(h2, Wfc, nullptr, uvb, BT, 8 * CDIM, CDIM);
    silu_kernel<<<(BT * 1024) / 256, 256>>>(uvb, suv, xb);
    mma_nt_kernel<false><<<dim3(CDIM / 128, BT / 128), 256, MMA_SMEM>>>(xb, Wproj, nullptr, t1, BT, CDIM, 4 * CDIM);

    residual_kernel<<<BT, 256>>>(h2, t1, a_mlp, out);
}

// round 3
// speedup vs baseline: 4.4153x; 2.2951x over previous
#include <cuda_runtime.h>
#include <cuda_bf16.h>
#include <math.h>
#include <stdint.h>

// nGPT block: B=8, T=1024, C=1024, H=16, D=64
#define BT   8192
#define CDIM 1024

// ---- scratch carve (float units) ----
#define OFF_INV  0
#define OFF_Q    4096
#define OFF_K    (OFF_Q   + BT*CDIM)
#define OFF_V    (OFF_K   + BT*CDIM)
#define OFF_T1   (OFF_V   + BT*CDIM)
#define OFF_H2   (OFF_T1  + BT*CDIM)
#define OFF_UV   (OFF_H2  + BT*CDIM)          // 8192x8192 fp32
#define OFF_HB   (OFF_UV  + BT*8*CDIM)        // bf16 regions below (float units)
#define OFF_YB   (OFF_HB  + BT*CDIM/2)
#define OFF_H2B  (OFF_YB  + BT*CDIM/2)
#define OFF_XB   (OFF_H2B + BT*CDIM/2)        // 8192x4096 bf16
#define OFF_WQB  (OFF_XB  + BT*4*CDIM/2)      // 4 matrices 1024x1024 bf16
#define OFF_WFCB (OFF_WQB + 4*CDIM*CDIM/2)
#define OFF_WPJB (OFF_WFCB + 8*CDIM*CDIM/2)
#define BUF_TOTAL (OFF_WPJB + 4*CDIM*CDIM/2)

__device__ float g_buf[BUF_TOTAL];

__device__ __forceinline__ uint32_t cvt2bf(float lo, float hi) {
    uint32_t r;
    asm("cvt.rn.bf16x2.f32 %0, %1, %2;" : "=r"(r) : "f"(hi), "f"(lo));
    return r;
}

// ---------------------------------------------------------------------------
// inverse column norms of W [C,C] row-major: inv[k] = 1/||W[:,k]||
// ---------------------------------------------------------------------------
__global__ void colnorm_kernel(const float* __restrict__ Wq, const float* __restrict__ Wk,
                               const float* __restrict__ Wv, const float* __restrict__ Wo,
                               float* __restrict__ inv)
{
    int m = blockIdx.y;
    const float* W = (m == 0) ? Wq : (m == 1) ? Wk : (m == 2) ? Wv : Wo;
    int tx = threadIdx.x & 31;
    int ty = threadIdx.x >> 5;
    int col = blockIdx.x * 32 + tx;
    float s = 0.f;
    for (int i = ty; i < CDIM; i += 8) {
        float w = W[i * CDIM + col];
        s += w * w;
    }
    __shared__ float sm[8][32];
    sm[ty][tx] = s;
    __syncthreads();
    if (ty == 0) {
        float tot = 0.f;
        #pragma unroll
        for (int r = 0; r < 8; r++) tot += sm[r][tx];
        inv[m * CDIM + col] = rsqrtf(tot);
    }
}

// ---------------------------------------------------------------------------
// Weight conversion: dst[n,k] = bf16( W[n,k] * inv[m*1024 + k] ) for 4 matrices
// grid (1024, 4), block 256; thread handles one float4.
// ---------------------------------------------------------------------------
__global__ void wconv4_kernel(const float* __restrict__ Wq, const float* __restrict__ Wk,
                              const float* __restrict__ Wv, const float* __restrict__ Wo,
                              const float* __restrict__ inv, uint32_t* __restrict__ dst)
{
    int m = blockIdx.y;
    const float* W = (m == 0) ? Wq : (m == 1) ? Wk : (m == 2) ? Wv : Wo;
    int idx = blockIdx.x * 256 + threadIdx.x;      // float4 id, 262144 per matrix
    float4 w = ((const float4*)W)[idx];
    float4 s = ((const float4*)(inv + m * CDIM))[idx & 255];
    uint32_t* d = dst + (size_t)m * (CDIM * CDIM / 2) + idx * 2;
    d[0] = cvt2bf(w.x * s.x, w.y * s.y);
    d[1] = cvt2bf(w.z * s.z, w.w * s.w);
}

// generic fp32 -> bf16 convert, one float4 per thread
__global__ void conv_kernel(const float* __restrict__ src, uint32_t* __restrict__ dst)
{
    int idx = blockIdx.x * 256 + threadIdx.x;
    float4 v = ((const float4*)src)[idx];
    dst[idx * 2 + 0] = cvt2bf(v.x, v.y);
    dst[idx * 2 + 1] = cvt2bf(v.z, v.w);
}

// ---------------------------------------------------------------------------
// bf16 tensor-core GEMM NT: C[m,n] = sum_k A[m,k]*B[n,k]   (fp32 accumulate)
// A [M,K], B [N,K] bf16 row-major. Tile 128x128x64, 3-stage cp.async pipeline,
// xor-swizzled smem + ldmatrix.x4, 8 warps (2x4), warp tile 64x32.
// ---------------------------------------------------------------------------
#define STAGES 3
#define GEMM_SMEM (STAGES * 32768)

__global__ void __launch_bounds__(256) bf16_nt_kernel(
    const __nv_bfloat16* __restrict__ A, const __nv_bfloat16* __restrict__ B,
    float* __restrict__ C, int M, int N, int K)
{
    extern __shared__ char smc[];
    const int tid = threadIdx.x, lane = tid & 31, warp = tid >> 5;
    const int wm = warp & 1, wn = warp >> 1;
    const int crow = blockIdx.y * 128, ccol = blockIdx.x * 128;
    const uint32_t sbase = (uint32_t)__cvta_generic_to_shared(smc);

    const __nv_bfloat16* Ag = A + (size_t)crow * K;
    const __nv_bfloat16* Bg = B + (size_t)ccol * K;

    // copy one 64-k tile into stage buffer
    auto issue = [&](int t, int buf) {
        const uint32_t abase = sbase + buf * 32768;
        const uint32_t bbase = abase + 16384;
        const int k0 = t * 64;
        #pragma unroll
        for (int i = 0; i < 4; i++) {
            int idx = tid + i * 256;
            int row = idx >> 3, c = idx & 7;
            uint32_t sw = (uint32_t)((c ^ (row & 7)) << 4);
            uint32_t da = abase + row * 128 + sw;
            const void* sa = Ag + (size_t)row * K + k0 + c * 8;
            asm volatile("cp.async.cg.shared.global [%0], [%1], 16;" :: "r"(da), "l"(sa));
            uint32_t db = bbase + row * 128 + sw;
            const void* sb = Bg + (size_t)row * K + k0 + c * 8;
            asm volatile("cp.async.cg.shared.global [%0], [%1], 16;" :: "r"(db), "l"(sb));
        }
    };

    float acc[4][4][4];
    #pragma unroll
    for (int i = 0; i < 4; i++)
        #pragma unroll
        for (int j = 0; j < 4; j++)
            #pragma unroll
            for (int e = 0; e < 4; e++) acc[i][j][e] = 0.f;

    const int nt = K / 64;

    #pragma unroll
    for (int s = 0; s < STAGES - 1; s++) {
        issue(s, s);
        asm volatile("cp.async.commit_group;");
    }

    // per-lane ldmatrix address components
    const int arow0 = wm * 64 + (lane & 15);        // + mi*16
    const int akb   = lane >> 4;                    // chunk low bit
    const int asw   = lane & 7;                     // row&7 (swizzle)
    const int brow0 = wn * 32 + (lane & 7) + ((lane >> 4) << 3);  // + nj2*16
    const int bkb   = (lane >> 3) & 1;

    for (int t = 0; t < nt; t++) {
        asm volatile("cp.async.wait_group %0;" :: "n"(STAGES - 2));
        __syncthreads();

        const int buf = t % STAGES;
        const uint32_t abase = sbase + buf * 32768;
        const uint32_t bbase = abase + 16384;

        #pragma unroll
        for (int ks = 0; ks < 4; ks++) {
            uint32_t a[4][4], br[2][4];
            const int ach = 2 * ks + akb;
            const int bch = 2 * ks + bkb;
            #pragma unroll
            for (int mi = 0; mi < 4; mi++) {
                uint32_t ad = abase + (uint32_t)(arow0 + mi * 16) * 128 +
                              (uint32_t)((ach ^ asw) << 4);
                asm volatile("ldmatrix.sync.aligned.m8n8.x4.shared.b16 {%0,%1,%2,%3}, [%4];"
                             : "=r"(a[mi][0]), "=r"(a[mi][1]), "=r"(a[mi][2]), "=r"(a[mi][3])
                             : "r"(ad));
            }
            #pragma unroll
            for (int nj2 = 0; nj2 < 2; nj2++) {
                uint32_t bd = bbase + (uint32_t)(brow0 + nj2 * 16) * 128 +
                              (uint32_t)((bch ^ asw) << 4);
                asm volatile("ldmatrix.sync.aligned.m8n8.x4.shared.b16 {%0,%1,%2,%3}, [%4];"
                             : "=r"(br[nj2][0]), "=r"(br[nj2][1]), "=r"(br[nj2][2]), "=r"(br[nj2][3])
                             : "r"(bd));
            }
            #pragma unroll
            for (int mi = 0; mi < 4; mi++)
                #pragma unroll
                for (int nj = 0; nj < 4; nj++) {
                    uint32_t b0 = br[nj >> 1][(nj & 1) * 2];
                    uint32_t b1 = br[nj >> 1][(nj & 1) * 2 + 1];
                    asm volatile(
                        "mma.sync.aligned.m16n8k16.row.col.f32.bf16.bf16.f32 "
                        "{%0,%1,%2,%3}, {%4,%5,%6,%7}, {%8,%9}, {%0,%1,%2,%3};"
                        : "+f"(acc[mi][nj][0]), "+f"(acc[mi][nj][1]),
                          "+f"(acc[mi][nj][2]), "+f"(acc[mi][nj][3])
                        : "r"(a[mi][0]), "r"(a[mi][1]), "r"(a[mi][2]), "r"(a[mi][3]),
                          "r"(b0), "r"(b1));
                }
        }
        __syncthreads();

        if (t + STAGES - 1 < nt) issue(t + STAGES - 1, (t + STAGES - 1) % STAGES);
        asm volatile("cp.async.commit_group;");
    }

    #pragma unroll
    for (int mi = 0; mi < 4; mi++) {
        const int r0 = crow + wm * 64 + mi * 16 + (lane >> 2);
        #pragma unroll
        for (int nj = 0; nj < 4; nj++) {
            const int c0 = ccol + wn * 32 + nj * 8 + 2 * (lane & 3);
            *(float2*)&C[(size_t)r0 * N + c0]       = make_float2(acc[mi][nj][0], acc[mi][nj][1]);
            *(float2*)&C[(size_t)(r0 + 8) * N + c0] = make_float2(acc[mi][nj][2], acc[mi][nj][3]);
        }
    }
}

// ---------------------------------------------------------------------------
// Per-(token,head) L2-normalize q,k over 64, apply sqk*32; fold sqrt(D)=8 into q.
// ---------------------------------------------------------------------------
__global__ void qknorm_kernel(float* __restrict__ q, float* __restrict__ k,
                              const float* __restrict__ sqk)
{
    int t = blockIdx.x, tid = threadIdx.x;
    float4* q4 = (float4*)q + (size_t)t * 256;
    float4* k4 = (float4*)k + (size_t)t * 256;
    float4 sc = ((const float4*)sqk)[tid];

    float4 v = q4[tid];
    float ss = v.x * v.x + v.y * v.y + v.z * v.z + v.w * v.w;
    #pragma unroll
    for (int off = 8; off >= 1; off >>= 1) ss += __shfl_xor_sync(0xffffffffu, ss, off);
    float r = rsqrtf(ss) * 32.f * 8.f;
    v.x *= r * sc.x; v.y *= r * sc.y; v.z *= r * sc.z; v.w *= r * sc.w;
    q4[tid] = v;

    v = k4[tid];
    ss = v.x * v.x + v.y * v.y + v.z * v.z + v.w * v.w;
    #pragma unroll
    for (int off = 8; off >= 1; off >>= 1) ss += __shfl_xor_sync(0xffffffffu, ss, off);
    r = rsqrtf(ss) * 32.f;
    v.x *= r * sc.x; v.y *= r * sc.y; v.z *= r * sc.z; v.w *= r * sc.w;
    k4[tid] = v;
}

// ---------------------------------------------------------------------------
// Flash attention (non-causal), fp32 math, y written bf16.
// ---------------------------------------------------------------------------
__global__ void __launch_bounds__(256) attn_kernel(
    const float* __restrict__ q, const float* __restrict__ k,
    const float* __restrict__ v, __nv_bfloat16* __restrict__ y)
{
    extern __shared__ float smd[];
    float* Qs = smd;
    float* KP = smd + 4096;
    float* Vs = smd + 8256;

    int tid = threadIdx.x;
    int tx = tid & 15, ty = tid >> 4;
    int bh    = blockIdx.y;
    int tbase = (bh >> 4) * 1024;
    int cb    = (bh & 15) * 64;
    int tq0   = tbase + blockIdx.x * 64;

    #pragma unroll
    for (int r = 0; r < 4; r++) {
        int idx = tid + r * 256;
        int i = idx >> 4, d4 = idx & 15;
        *(float4*)&Qs[i * 64 + d4 * 4] =
            *(const float4*)&q[(size_t)(tq0 + i) * CDIM + cb + d4 * 4];
    }

    float acc[4][4], mrow[4], lrow[4];
    #pragma unroll
    for (int r = 0; r < 4; r++) {
        mrow[r] = -1e30f; lrow[r] = 0.f;
        #pragma unroll
        for (int c = 0; c < 4; c++) acc[r][c] = 0.f;
    }

    for (int kt = 0; kt < 16; kt++) {
        int tk0 = tbase + kt * 64;
        __syncthreads();
        #pragma unroll
        for (int r = 0; r < 4; r++) {
            int idx = tid + r * 256;
            int j = idx >> 4, d4 = idx & 15;
            float4 kv = *(const float4*)&k[(size_t)(tk0 + j) * CDIM + cb + d4 * 4];
            KP[(d4 * 4 + 0) * 65 + j] = kv.x;
            KP[(d4 * 4 + 1) * 65 + j] = kv.y;
            KP[(d4 * 4 + 2) * 65 + j] = kv.z;
            KP[(d4 * 4 + 3) * 65 + j] = kv.w;
            *(float4*)&Vs[j * 64 + d4 * 4] =
                *(const float4*)&v[(size_t)(tk0 + j) * CDIM + cb + d4 * 4];
        }
        __syncthreads();

        float s[4][4];
        #pragma unroll
        for (int r = 0; r < 4; r++)
            #pragma unroll
            for (int c = 0; c < 4; c++) s[r][c] = 0.f;
        #pragma unroll 8
        for (int d = 0; d < 64; d++) {
            float qr[4], kcv[4];
            #pragma unroll
            for (int r = 0; r < 4; r++) qr[r] = Qs[(4 * ty + r) * 64 + d];
            #pragma unroll
            for (int c = 0; c < 4; c++) kcv[c] = KP[d * 65 + 4 * tx + c];
            #pragma unroll
            for (int r = 0; r < 4; r++)
                #pragma unroll
                for (int c = 0; c < 4; c++) s[r][c] += qr[r] * kcv[c];
        }

        float co[4];
        #pragma unroll
        for (int r = 0; r < 4; r++) {
            float rm = fmaxf(fmaxf(s[r][0], s[r][1]), fmaxf(s[r][2], s[r][3]));
            #pragma unroll
            for (int off = 8; off >= 1; off >>= 1)
                rm = fmaxf(rm, __shfl_xor_sync(0xffffffffu, rm, off));
            float mn = fmaxf(mrow[r], rm);
            co[r] = __expf(mrow[r] - mn);
            float ls = 0.f;
            #pragma unroll
            for (int c = 0; c < 4; c++) {
                float e = __expf(s[r][c] - mn);
                s[r][c] = e; ls += e;
            }
            #pragma unroll
            for (int off = 8; off >= 1; off >>= 1)
                ls += __shfl_xor_sync(0xffffffffu, ls, off);
            lrow[r] = lrow[r] * co[r] + ls;
            mrow[r] = mn;
        }

        __syncthreads();
        #pragma unroll
        for (int r = 0; r < 4; r++)
            #pragma unroll
            for (int c = 0; c < 4; c++)
                KP[(4 * ty + r) * 65 + 4 * tx + c] = s[r][c];
        __syncthreads();

        #pragma unroll
        for (int r = 0; r < 4; r++)
            #pragma unroll
            for (int c = 0; c < 4; c++) acc[r][c] *= co[r];

        #pragma unroll 8
        for (int j = 0; j < 64; j++) {
            float pr[4], vc[4];
            #pragma unroll
            for (int r = 0; r < 4; r++) pr[r] = KP[(4 * ty + r) * 65 + j];
            #pragma unroll
            for (int c = 0; c < 4; c++) vc[c] = Vs[j * 64 + 4 * tx + c];
            #pragma unroll
            for (int r = 0; r < 4; r++)
                #pragma unroll
                for (int c = 0; c < 4; c++) acc[r][c] += pr[r] * vc[c];
        }
    }

    #pragma unroll
    for (int r = 0; r < 4; r++) {
        float li = 1.f / lrow[r];
        uint32_t p0 = cvt2bf(acc[r][0] * li, acc[r][1] * li);
        uint32_t p1 = cvt2bf(acc[r][2] * li, acc[r][3] * li);
        *(uint2*)&y[(size_t)(tq0 + 4 * ty + r) * CDIM + cb + 4 * tx] = make_uint2(p0, p1);
    }
}

// ---------------------------------------------------------------------------
// x[t,m] = (suv[m]*32*uv[t,m]) * silu(suv[m+4096]*32*uv[t,m+4096]) -> bf16
// ---------------------------------------------------------------------------
__global__ void silu_kernel(const float* __restrict__ uv, const float* __restrict__ suv,
                            uint32_t* __restrict__ x)
{
    int idx = blockIdx.x * 256 + threadIdx.x;
    int t = idx >> 10, m4 = idx & 1023;
    const float4* uv4 = (const float4*)uv;
    const float4* s4  = (const float4*)suv;
    float4 u  = uv4[(size_t)t * 2048 + m4];
    float4 g  = uv4[(size_t)t * 2048 + 1024 + m4];
    float4 su = s4[m4];
    float4 sg = s4[1024 + m4];
    float4 o;
    float gx;
    gx = g.x * sg.x * 32.f; o.x = (u.x * su.x * 32.f) * gx / (1.f + __expf(-gx));
    gx = g.y * sg.y * 32.f; o.y = (u.y * su.y * 32.f) * gx / (1.f + __expf(-gx));
    gx = g.z * sg.z * 32.f; o.z = (u.z * su.z * 32.f) * gx / (1.f + __expf(-gx));
    gx = g.w * sg.w * 32.f; o.w = (u.w * su.w * 32.f) * gx / (1.f + __expf(-gx));
    x[(size_t)idx * 2 + 0] = cvt2bf(o.x, o.y);
    x[(size_t)idx * 2 + 1] = cvt2bf(o.z, o.w);
}

// ---------------------------------------------------------------------------
// out = justnorm( justnorm(h) + |alpha*1.6| * (justnorm(hb) - justnorm(h)) )
// optional bf16 copy of out.
// ---------------------------------------------------------------------------
__global__ void residual_kernel(const float* __restrict__ hin, const float* __restrict__ hb,
                                const float* __restrict__ alpha, float* __restrict__ out,
                                uint32_t* __restrict__ outb)
{
    int t = blockIdx.x, tid = threadIdx.x;
    float4 a = ((const float4*)hin)[(size_t)t * 256 + tid];
    float4 b = ((const float4*)hb)[(size_t)t * 256 + tid];
    float s1 = a.x * a.x + a.y * a.y + a.z * a.z + a.w * a.w;
    float s2 = b.x * b.x + b.y * b.y + b.z * b.z + b.w * b.w;
    #pragma unroll
    for (int off = 16; off >= 1; off >>= 1) {
        s1 += __shfl_xor_sync(0xffffffffu, s1, off);
        s2 += __shfl_xor_sync(0xffffffffu, s2, off);
    }
    __shared__ float red1[8], red2[8];
    int w = tid >> 5, lane = tid & 31;
    if (lane == 0) { red1[w] = s1; red2[w] = s2; }
    __syncthreads();
    float t1 = 0.f, t2 = 0.f;
    #pragma unroll
    for (int i = 0; i < 8; i++) { t1 += red1[i]; t2 += red2[i]; }
    float r1 = rsqrtf(t1), r2 = rsqrtf(t2);

    float4 al = ((const float4*)alpha)[tid];
    float4 u;
    u.x = a.x * r1 + fabsf(al.x * 1.6f) * (b.x * r2 - a.x * r1);
    u.y = a.y * r1 + fabsf(al.y * 1.6f) * (b.y * r2 - a.y * r1);
    u.z = a.z * r1 + fabsf(al.z * 1.6f) * (b.z * r2 - a.z * r1);
    u.w = a.w * r1 + fabsf(al.w * 1.6f) * (b.w * r2 - a.w * r1);

    float s3 = u.x * u.x + u.y * u.y + u.z * u.z + u.w * u.w;
    #pragma unroll
    for (int off = 16; off >= 1; off >>= 1) s3 += __shfl_xor_sync(0xffffffffu, s3, off);
    __syncthreads();
    if (lane == 0) red1[w] = s3;
    __syncthreads();
    float t3 = 0.f;
    #pragma unroll
    for (int i = 0; i < 8; i++) t3 += red1[i];
    float r3 = rsqrtf(t3);
    float4 o = make_float4(u.x * r3, u.y * r3, u.z * r3, u.w * r3);
    ((float4*)out)[(size_t)t * 256 + tid] = o;
    if (outb) {
        outb[((size_t)t * 256 + tid) * 2 + 0] = cvt2bf(o.x, o.y);
        outb[((size_t)t * 256 + tid) * 2 + 1] = cvt2bf(o.z, o.w);
    }
}

// ---------------------------------------------------------------------------
extern "C" void kernel_launch(void* const* d_in, const int* in_sizes, int n_in,
                              void* d_out, int out_size)
{
    (void)in_sizes; (void)n_in; (void)out_size;
    const float* h     = (const float*)d_in[0];
    const float* Wq    = (const float*)d_in[1];
    const float* Wk    = (const float*)d_in[2];
    const float* Wv    = (const float*)d_in[3];
    const float* Wo    = (const float*)d_in[4];
    const float* Wfc   = (const float*)d_in[5];
    const float* Wproj = (const float*)d_in[6];
    const float* sqk   = (const float*)d_in[7];
    const float* suv   = (const float*)d_in[8];
    const float* a_att = (const float*)d_in[9];
    const float* a_mlp = (const float*)d_in[10];
    float* out = (float*)d_out;

    float* buf = nullptr;
    cudaGetSymbolAddress((void**)&buf, g_buf);
    float* inv = buf + OFF_INV;
    float* qb  = buf + OFF_Q;
    float* kb  = buf + OFF_K;
    float* vb  = buf + OFF_V;
    float* t1  = buf + OFF_T1;
    float* h2  = buf + OFF_H2;
    float* uvb = buf + OFF_UV;
    __nv_bfloat16* hB   = (__nv_bfloat16*)(buf + OFF_HB);
    __nv_bfloat16* yB   = (__nv_bfloat16*)(buf + OFF_YB);
    __nv_bfloat16* h2B  = (__nv_bfloat16*)(buf + OFF_H2B);
    __nv_bfloat16* xB   = (__nv_bfloat16*)(buf + OFF_XB);
    __nv_bfloat16* WqB  = (__nv_bfloat16*)(buf + OFF_WQB);
    __nv_bfloat16* WkB  = WqB + CDIM * CDIM;
    __nv_bfloat16* WvB  = WkB + CDIM * CDIM;
    __nv_bfloat16* WoB  = WvB + CDIM * CDIM;
    __nv_bfloat16* WfcB = (__nv_bfloat16*)(buf + OFF_WFCB);
    __nv_bfloat16* WpjB = (__nv_bfloat16*)(buf + OFF_WPJB);

    cudaFuncSetAttribute(attn_kernel, cudaFuncAttributeMaxDynamicSharedMemorySize, 49408);
    cudaFuncSetAttribute(bf16_nt_kernel, cudaFuncAttributeMaxDynamicSharedMemorySize, GEMM_SMEM);

    // weight norms + conversions
    colnorm_kernel<<<dim3(32, 4), 256>>>(Wq, Wk, Wv, Wo, inv);
    wconv4_kernel<<<dim3(1024, 4), 256>>>(Wq, Wk, Wv, Wo, inv, (uint32_t*)WqB);
    conv_kernel<<<8 * CDIM * CDIM / 1024, 256>>>(Wfc,   (uint32_t*)WfcB);
    conv_kernel<<<4 * CDIM * CDIM / 1024, 256>>>(Wproj, (uint32_t*)WpjB);
    conv_kernel<<<BT * CDIM / 1024, 256>>>(h, (uint32_t*)hB);

    // q,k,v projections
    dim3 gqkv(CDIM / 128, BT / 128);
    bf16_nt_kernel<<<gqkv, 256, GEMM_SMEM>>>(hB, WqB, qb, BT, CDIM, CDIM);
    bf16_nt_kernel<<<gqkv, 256, GEMM_SMEM>>>(hB, WkB, kb, BT, CDIM, CDIM);
    bf16_nt_kernel<<<gqkv, 256, GEMM_SMEM>>>(hB, WvB, vb, BT, CDIM, CDIM);

    qknorm_kernel<<<BT, 256>>>(qb, kb, sqk);

    attn_kernel<<<dim3(16, 128), 256, 49408>>>(qb, kb, vb, yB);

    bf16_nt_kernel<<<gqkv, 256, GEMM_SMEM>>>(yB, WoB, t1, BT, CDIM, CDIM);

    residual_kernel<<<BT, 256>>>(h, t1, a_att, h2, (uint32_t*)h2B);

    bf16_nt_kernel<<<dim3(8 * CDIM / 128, BT / 128), 256, GEMM_SMEM>>>(h2B, WfcB, uvb, BT, 8 * CDIM, CDIM);
    silu_kernel<<<(BT * 1024) / 256, 256>>>(uvb, suv, (uint32_t*)xB);
    bf16_nt_kernel<<<dim3(CDIM / 128, BT / 128), 256, GEMM_SMEM>>>(xB, WpjB, t1, BT, CDIM, 4 * CDIM);

    residual_kernel<<<BT, 256>>>(h2, t1, a_mlp, out, nullptr);
}